// round 9
// baseline (speedup 1.0000x reference)
#include <cuda_runtime.h>

#define B_      32
#define NOTES_  78
#define T_      128
#define IN_     80
#define H_      128
#define NSEQ1   (B_ * NOTES_)          // 2496
#define SPB     17                      // sequences per block
#define NBLK    147                     // 147*17 = 2499 >= 2496, 1 block/SM
#define KK2     52                      // float4 k-slices per gate row (208 scalars / 4)
#define KK2PAD  56                      // padded for unconditional ring prefetch

// ---------------- device scratch (no allocations allowed) ----------------
__device__ float4 g_wpk4[KK2PAD * 512];                    // packed weights [kk2][row]
__device__ float  g_xpj[(size_t)NSEQ1 * T_ * 8];           // fused note-LSTM input projection

// ---------------- helpers ----------------
__device__ __forceinline__ float2 upk2(unsigned long long v) {
    float lo, hi;
    asm("mov.b64 {%0,%1}, %2;" : "=f"(lo), "=f"(hi) : "l"(v));
    float2 f; f.x = lo; f.y = hi; return f;
}
__device__ __forceinline__ void fma2(unsigned long long& a, unsigned long long w, unsigned long long d) {
    asm("fma.rn.f32x2 %0, %1, %2, %0;" : "+l"(a) : "l"(w), "l"(d));
}
__device__ __forceinline__ float sigf(float x)     { return __fdividef(1.f, 1.f + __expf(-x)); }
__device__ __forceinline__ float tanhfast(float x) { return 2.f * sigf(2.f * x) - 1.f; }
__device__ __forceinline__ unsigned smem_u32(const void* p) {
    unsigned a;
    asm("{ .reg .u64 t; cvta.to.shared.u64 t, %1; cvt.u32.u64 %0, t; }" : "=r"(a) : "l"(p));
    return a;
}

// ---------------- weight packing: [kk2][512] float4, k-major quads ----------------
__global__ void pack_w_kernel(const float* __restrict__ Wih, const float* __restrict__ Whh) {
    int idx = blockIdx.x * blockDim.x + threadIdx.x;
    if (idx >= KK2PAD * 512) return;
    int kk2 = idx >> 9;
    int r   = idx & 511;
    int k0  = 4 * kk2;
    float v[4];
    #pragma unroll
    for (int l = 0; l < 4; l++) {
        int k = k0 + l;
        float val = 0.f;
        if (k < IN_)                 val = Wih[r * IN_ + k];
        else if (k < IN_ + H_)       val = Whh[r * H_ + (k - IN_)];
        v[l] = val;
    }
    g_wpk4[kk2 * 512 + r] = make_float4(v[0], v[1], v[2], v[3]);
}

__global__ void sink_kernel() {}

// ---------------- stage 1: time LSTM, persistent, 512 thr = 1 row/thread ----------------
// row r = tid; gate = tid>>7 (0=i,1=f,2=g,3=o); j = tid&127.
// SMEM (dynamic): sdata[17][208] floats (x[0:80) | h[80:208)), act[4][128][17], sWn[8*128]
__global__ __launch_bounds__(512, 1) void stage1_kernel(
    const float* __restrict__ x,
    const float* __restrict__ bih, const float* __restrict__ bhh,
    const float* __restrict__ Wihn)
{
    extern __shared__ float smem[];
    float*  df   = smem;                        // 17*208 = 3536 floats
    float*  sact = smem + SPB * 208;            // 4*128*17 = 8704 floats
    float*  sWn  = sact + 4 * 128 * SPB;        // 1024 floats

    const int tid  = threadIdx.x;
    const int seq0 = blockIdx.x * SPB;
    const int gate = tid >> 7;
    const int j    = tid & 127;
    const float bias = bih[tid] + bhh[tid];

    for (int i = tid; i < 8 * H_; i += 512) sWn[i] = Wihn[i];
    for (int i = tid; i < SPB * 208; i += 512) df[i] = 0.f;   // zero h region (x overwritten)

    float c[SPB];
    #pragma unroll
    for (int s = 0; s < SPB; s++) c[s] = 0.f;

    const unsigned sb = smem_u32(df);
    const char* gw = reinterpret_cast<const char*>(g_wpk4);

    // x prefetch registers: threads 0..339 each hold one float4 of x(t)
    const int xs = tid / 20, xq = tid - xs * 20;   // valid when tid < 340
    float4 xr = make_float4(0, 0, 0, 0);
    float4* df4 = reinterpret_cast<float4*>(df);
    const float4* xg4 = reinterpret_cast<const float4*>(x);
    if (tid < SPB * 20) {
        int seq = seq0 + xs; if (seq >= NSEQ1) seq = NSEQ1 - 1;
        xr = xg4[((size_t)seq * T_ + 0) * 20 + xq];
    }

    for (int t = 0; t < T_; t++) {
        // ---- stage x(t) from registers into SMEM ----
        if (tid < SPB * 20) df4[xs * 52 + xq] = xr;
        __syncthreads();                       // x(t) & h(t-1) ready

        // ---- issue x(t+1) prefetch (latency hidden under matvec) ----
        if (tid < SPB * 20) {
            int tn = (t + 1 < T_) ? t + 1 : t;
            int seq = seq0 + xs; if (seq >= NSEQ1) seq = NSEQ1 - 1;
            xr = xg4[((size_t)seq * T_ + tn) * 20 + xq];
        }

        // ---- matvec: gate row tid over [x;h] for 17 seqs, f32x2 + 128-bit loads ----
        unsigned long long acc[SPB];
        #pragma unroll
        for (int s = 0; s < SPB; s++) acc[s] = 0ull;

        unsigned long long wr[4][2];           // ring: 4 float4 in flight
        #pragma unroll
        for (int p = 0; p < 4; p++)
            asm("ld.global.nc.v2.b64 {%0,%1}, [%2];"
                : "=l"(wr[p][0]), "=l"(wr[p][1])
                : "l"(gw + ((size_t)p * 512 + tid) * 16));

        #pragma unroll 4
        for (int i2 = 0; i2 < KK2; i2++) {
            const unsigned long long cw0 = wr[i2 & 3][0], cw1 = wr[i2 & 3][1];
            asm("ld.global.nc.v2.b64 {%0,%1}, [%2];"
                : "=l"(wr[i2 & 3][0]), "=l"(wr[i2 & 3][1])
                : "l"(gw + ((size_t)(i2 + 4) * 512 + tid) * 16));
            #pragma unroll
            for (int s = 0; s < SPB; s++) {
                unsigned long long d01, d23;
                asm("ld.shared.v2.b64 {%0,%1}, [%2];"
                    : "=l"(d01), "=l"(d23)
                    : "r"(sb + (unsigned)(s * 832 + i2 * 16)));
                fma2(acc[s], cw0, d01);
                fma2(acc[s], cw1, d23);
            }
        }

        // ---- activations (all 512 threads) -> act exchange ----
        #pragma unroll
        for (int s = 0; s < SPB; s++) {
            float2 a = upk2(acc[s]);
            float g = a.x + a.y + bias;
            float av = (gate == 2) ? tanhfast(g) : sigf(g);
            sact[gate * (128 * SPB) + j * SPB + s] = av;
        }
        __syncthreads();                       // act ready; matvec reads done

        // ---- cell update + h(t) write (threads 0..127 own cell j) ----
        if (tid < 128) {
            #pragma unroll
            for (int s = 0; s < SPB; s++) {
                float ai = sact[0 * (128 * SPB) + j * SPB + s];
                float af = sact[1 * (128 * SPB) + j * SPB + s];
                float ag = sact[2 * (128 * SPB) + j * SPB + s];
                float ao = sact[3 * (128 * SPB) + j * SPB + s];
                c[s] = af * c[s] + ai * ag;
                df[s * 208 + 80 + j] = ao * tanhfast(c[s]);
            }
        }
        __syncthreads();                       // h(t) ready

        // ---- fused note-LSTM input projection (136 threads; others run ahead) ----
        if (tid < SPB * 8) {
            int s = tid >> 3, row = tid & 7;
            const float2* hv = reinterpret_cast<const float2*>(&df[s * 208 + 80]);
            const float2* wv = reinterpret_cast<const float2*>(&sWn[row * H_]);
            float a = 0.f;
            #pragma unroll
            for (int jj = 0; jj < 64; jj++) {
                float2 h2 = hv[jj], w2 = wv[jj];
                a = fmaf(h2.x, w2.x, fmaf(h2.y, w2.y, a));
            }
            int seq = seq0 + s;
            if (seq < NSEQ1) g_xpj[((size_t)seq * T_ + t) * 8 + row] = a;
        }
        // next iteration's x-store region is disjoint from h; its sync orders the rest
    }
}

// ---------------- stage 2: note LSTM (hidden=2), one thread per (b,t) ----------------
__global__ __launch_bounds__(128) void stage2_kernel(
    const float* __restrict__ Whhn,
    const float* __restrict__ bihn, const float* __restrict__ bhhn,
    float* __restrict__ out)
{
    int g = blockIdx.x * 128 + threadIdx.x;    // 0..4095
    int b = g >> 7, t = g & 127;

    float W[16];
    #pragma unroll
    for (int i = 0; i < 16; i++) W[i] = Whhn[i];
    float bs[8];
    #pragma unroll
    for (int i = 0; i < 8; i++) bs[i] = bihn[i] + bhhn[i];

    float h0 = 0.f, h1 = 0.f, c0 = 0.f, c1 = 0.f;
    const float4* xp = reinterpret_cast<const float4*>(g_xpj);
    float* op = out + ((size_t)b * T_ + t) * (NOTES_ * 2);

    for (int note = 0; note < NOTES_; note++) {
        size_t base = ((size_t)(b * NOTES_ + note) * T_ + t) * 2;
        float4 xa = xp[base];       // rows 0..3 : i0 i1 f0 f1
        float4 xb = xp[base + 1];   // rows 4..7 : g0 g1 o0 o1
        float gi0 = xa.x + bs[0] + W[0]  * h0 + W[1]  * h1;
        float gi1 = xa.y + bs[1] + W[2]  * h0 + W[3]  * h1;
        float gf0 = xa.z + bs[2] + W[4]  * h0 + W[5]  * h1;
        float gf1 = xa.w + bs[3] + W[6]  * h0 + W[7]  * h1;
        float gg0 = xb.x + bs[4] + W[8]  * h0 + W[9]  * h1;
        float gg1 = xb.y + bs[5] + W[10] * h0 + W[11] * h1;
        float go0 = xb.z + bs[6] + W[12] * h0 + W[13] * h1;
        float go1 = xb.w + bs[7] + W[14] * h0 + W[15] * h1;
        c0 = sigf(gf0) * c0 + sigf(gi0) * tanhfast(gg0);
        c1 = sigf(gf1) * c1 + sigf(gi1) * tanhfast(gg1);
        h0 = sigf(go0) * tanhfast(c0);
        h1 = sigf(go1) * tanhfast(c1);
        op[note * 2]     = h0;
        op[note * 2 + 1] = h1;
    }
}

// ---------------- launch ----------------
extern "C" void kernel_launch(void* const* d_in, const int* in_sizes, int n_in,
                              void* d_out, int out_size)
{
    const float* x     = (const float*)d_in[0];
    const float* Wih_t = (const float*)d_in[1];
    const float* Whh_t = (const float*)d_in[2];
    const float* bih_t = (const float*)d_in[3];
    const float* bhh_t = (const float*)d_in[4];
    const float* Wih_n = (const float*)d_in[5];
    const float* Whh_n = (const float*)d_in[6];
    const float* bih_n = (const float*)d_in[7];
    const float* bhh_n = (const float*)d_in[8];
    float* out = (float*)d_out;

    const int smem_bytes = (SPB * 208 + 4 * 128 * SPB + 8 * H_) * sizeof(float); // 53056
    cudaFuncSetAttribute(stage1_kernel, cudaFuncAttributeMaxDynamicSharedMemorySize, smem_bytes);

    // 4 launches/call so ncu (-s 5 -c 1) lands on stage1 (global launch #6)
    pack_w_kernel<<<(KK2PAD * 512 + 255) / 256, 256>>>(Wih_t, Whh_t);
    stage1_kernel<<<NBLK, 512, smem_bytes>>>(x, bih_t, bhh_t, Wih_n);
    stage2_kernel<<<(B_ * T_) / 128, 128>>>(Whh_n, bih_n, bhh_n, out);
    sink_kernel<<<1, 32>>>();
}

// round 10
// speedup vs baseline: 1.5702x; 1.5702x over previous
#include <cuda_runtime.h>
#include <cuda_bf16.h>
#include <cstdint>

#define B_     32
#define NOTES_ 78
#define T_     128
#define NSEQ   2496
#define SPB1   24

// ---------------- device scratch (no allocations allowed) ----------------
__device__ uint32_t g_whhA[2 * 8 * 32 * 128];           // [hf][kt][mt][lane*4+q] A-frag image
__device__ uint32_t g_wxA [2 * 5 * 32 * 128];           // same for Wih_t (K=80)
__device__ float    g_xpre[(size_t)T_ * 512 * NSEQ];    // x-projection [t][row][seq]
__device__ float    g_xpj[(size_t)NSEQ * T_ * 8];       // fused note-LSTM input proj

// ---------------- helpers ----------------
__device__ __forceinline__ float sigf(float x)   { return __fdividef(1.f, 1.f + __expf(-x)); }
__device__ __forceinline__ float tanhf_(float x) { return 2.f * sigf(2.f * x) - 1.f; }

__device__ __forceinline__ uint32_t bfhi2(float a, float b) {
    __nv_bfloat162 t = __floats2bfloat162_rn(a, b);     // .x (low) = a
    return *reinterpret_cast<uint32_t*>(&t);
}
__device__ __forceinline__ uint32_t bflo2(float a, float b) {
    __nv_bfloat16 ha = __float2bfloat16_rn(a), hb = __float2bfloat16_rn(b);
    return bfhi2(a - __bfloat162float(ha), b - __bfloat162float(hb));
}
__device__ __forceinline__ void mma_bf16(float* c, const uint32_t* a, uint32_t b0, uint32_t b1) {
    asm volatile(
        "mma.sync.aligned.m16n8k16.row.col.f32.bf16.bf16.f32 "
        "{%0,%1,%2,%3},{%4,%5,%6,%7},{%8,%9},{%0,%1,%2,%3};"
        : "+f"(c[0]), "+f"(c[1]), "+f"(c[2]), "+f"(c[3])
        : "r"(a[0]), "r"(a[1]), "r"(a[2]), "r"(a[3]), "r"(b0), "r"(b1));
}

// ---------------- pack: build A-fragment images (hi/lo bf16 split) ----------------
__global__ void pack_kernel(const float* __restrict__ Wih, const float* __restrict__ Whh) {
    int i = blockIdx.x * 256 + threadIdx.x;
    if (i < 65536) {                         // Whh: [hf][kt(8)][mt(32)][lane][q]
        int q = i & 3, lane = (i >> 2) & 31, hf = i >> 15;
        int row = ((i >> 7) & 31) * 16 + (lane >> 2) + (q & 1) * 8;
        int k   = ((i >> 12) & 7) * 16 + 2 * (lane & 3) + (q >> 1) * 8;
        float v0 = Whh[row * 128 + k], v1 = Whh[row * 128 + k + 1];
        g_whhA[i] = hf ? bflo2(v0, v1) : bfhi2(v0, v1);
    } else if (i < 65536 + 40960) {          // Wih: [hf][kt(5)][mt][lane][q]
        int j = i - 65536;
        int q = j & 3, lane = (j >> 2) & 31;
        int r = j >> 12, kt = r % 5, hf = r / 5;
        int row = ((j >> 7) & 31) * 16 + (lane >> 2) + (q & 1) * 8;
        int k   = kt * 16 + 2 * (lane & 3) + (q >> 1) * 8;
        float v0 = Wih[row * 80 + k], v1 = Wih[row * 80 + k + 1];
        g_wxA[j] = hf ? bflo2(v0, v1) : bfhi2(v0, v1);
    }
}

__global__ void dummy_kernel() {}

// ---------------- xproj: g_xpre[t][row][seq] = Wih_t . x  (tensor cores) ----------------
// grid = 39 seq-tiles x 32 t-groups (4 t each); block 512 thr = 16 warps (2 Mtiles x 8 Ntiles)
__global__ __launch_bounds__(512, 1) void xproj_kernel(const float* __restrict__ x) {
    extern __shared__ uint32_t smx[];
    uint32_t* sWx = smx;                     // 40960 u32
    uint32_t* sB  = smx + 40960;             // [hf][kt5][nt8][lane][2] = 5120 u32
    const int tid = threadIdx.x, w = tid >> 5, lane = tid & 31;
    const int sg0 = (blockIdx.x >> 5) * 64;
    const int tb  = (blockIdx.x & 31) * 4;

    for (int i = tid; i < 40960; i += 512) sWx[i] = g_wxA[i];

    for (int tt = 0; tt < 4; tt++) {
        const int t = tb + tt;
        __syncthreads();                     // sWx ready / prev sB reads done
        // stage x(t) for 64 seqs, split hi/lo into B-frag layout
        for (int r = 0; r < 3; r++) {
            int idx = tid + r * 512;
            if (idx < 1280) {
                int s = idx / 20, qq = idx - s * 20, k0 = qq * 4;
                float4 v = *reinterpret_cast<const float4*>(&x[((size_t)(sg0 + s) * T_ + t) * 80 + k0]);
                int kt = k0 >> 4, kk = k0 & 15, nt = s >> 3;
                int lb = (s & 7) * 4 + ((kk & 7) >> 1), reg = kk >> 3;
                uint32_t* ph = &sB[((0 * 5 + kt) * 8 + nt) * 64 + lb * 2 + reg];
                uint32_t* pl = &sB[((1 * 5 + kt) * 8 + nt) * 64 + lb * 2 + reg];
                ph[0] = bfhi2(v.x, v.y); ph[2] = bfhi2(v.z, v.w);
                pl[0] = bflo2(v.x, v.y); pl[2] = bflo2(v.z, v.w);
            }
        }
        __syncthreads();

        float C[2][8][4];
        #pragma unroll
        for (int a = 0; a < 2; a++)
            #pragma unroll
            for (int n = 0; n < 8; n++)
                #pragma unroll
                for (int q = 0; q < 4; q++) C[a][n][q] = 0.f;

        #pragma unroll
        for (int kt = 0; kt < 5; kt++) {
            uint32_t Ah[2][4], Al[2][4];
            #pragma unroll
            for (int mt = 0; mt < 2; mt++) {
                const uint32_t* p  = &sWx[((0 * 5 + kt) * 32 + (2 * w + mt)) * 128 + lane * 4];
                const uint32_t* p2 = &sWx[((1 * 5 + kt) * 32 + (2 * w + mt)) * 128 + lane * 4];
                #pragma unroll
                for (int q = 0; q < 4; q++) { Ah[mt][q] = p[q]; Al[mt][q] = p2[q]; }
            }
            #pragma unroll
            for (int nt = 0; nt < 8; nt++) {
                uint32_t bh0 = sB[((0 * 5 + kt) * 8 + nt) * 64 + lane * 2];
                uint32_t bh1 = sB[((0 * 5 + kt) * 8 + nt) * 64 + lane * 2 + 1];
                uint32_t bl0 = sB[((1 * 5 + kt) * 8 + nt) * 64 + lane * 2];
                uint32_t bl1 = sB[((1 * 5 + kt) * 8 + nt) * 64 + lane * 2 + 1];
                #pragma unroll
                for (int mt = 0; mt < 2; mt++) {
                    mma_bf16(C[mt][nt], Ah[mt], bh0, bh1);
                    mma_bf16(C[mt][nt], Al[mt], bh0, bh1);
                    mma_bf16(C[mt][nt], Ah[mt], bl0, bl1);
                }
            }
        }
        // store D -> g_xpre[t][row][seq]
        #pragma unroll
        for (int mt = 0; mt < 2; mt++)
            #pragma unroll
            for (int nt = 0; nt < 8; nt++) {
                int row = (2 * w + mt) * 16 + (lane >> 2);
                int sq  = sg0 + nt * 8 + 2 * (lane & 3);
                float* d = &g_xpre[((size_t)t * 512 + row) * NSEQ + sq];
                *reinterpret_cast<float2*>(d) = make_float2(C[mt][nt][0], C[mt][nt][1]);
                *reinterpret_cast<float2*>(d + (size_t)8 * NSEQ) = make_float2(C[mt][nt][2], C[mt][nt][3]);
            }
    }
}

// ---------------- stage 1: recurrent time LSTM on warp MMA ----------------
// 104 blocks x 24 seqs; 512 thr = 16 warps (2 Mtiles x 3 Ntiles each)
__global__ __launch_bounds__(512, 1) void stage1_kernel(
    const float* __restrict__ bih, const float* __restrict__ bhh,
    const float* __restrict__ Wihn)
{
    extern __shared__ uint32_t sm1[];
    uint32_t* sW   = sm1;                                // 32768 u32: Whh-hi frag image
    uint16_t* sB16 = (uint16_t*)(sm1 + 32768);           // [hf][kt8][nt3][lane][4] u16
    float*    sact = (float*)(sm1 + 32768 + 3072);       // [512][24]
    float*    sh   = sact + 512 * 24;                    // [24][128]
    float*    sWn  = sh + 24 * 128;                      // 1024

    const int tid = threadIdx.x, w = tid >> 5, lane = tid & 31;
    const int sg0 = blockIdx.x * SPB1;
    const int j = tid >> 2, sgrp = tid & 3;

    for (int i = tid; i < 32768; i += 512) sW[i] = g_whhA[i];
    for (int i = tid; i < 3072; i += 512) ((uint32_t*)sB16)[i] = 0;   // h(−1)=0
    for (int i = tid; i < 1024; i += 512) sWn[i] = Wihn[i];

    // Whh-lo fragments in registers
    uint32_t wlo[2][8][4];
    #pragma unroll
    for (int mt = 0; mt < 2; mt++)
        #pragma unroll
        for (int kt = 0; kt < 8; kt++) {
            const uint4 v = *reinterpret_cast<const uint4*>(
                &g_whhA[32768 + (kt * 32 + (2 * w + mt)) * 128 + lane * 4]);
            wlo[mt][kt][0] = v.x; wlo[mt][kt][1] = v.y; wlo[mt][kt][2] = v.z; wlo[mt][kt][3] = v.w;
        }

    const float bi_ = bih[j]       + bhh[j];
    const float bf_ = bih[128 + j] + bhh[128 + j];
    const float bg_ = bih[256 + j] + bhh[256 + j];
    const float bo_ = bih[384 + j] + bhh[384 + j];
    float cs[6] = {0, 0, 0, 0, 0, 0};

    __syncthreads();

    for (int t = 0; t < T_; t++) {
        // ---- C init from precomputed x-projection ----
        float C[2][3][4];
        #pragma unroll
        for (int mt = 0; mt < 2; mt++)
            #pragma unroll
            for (int nt = 0; nt < 3; nt++) {
                int row = (2 * w + mt) * 16 + (lane >> 2);
                int sq  = sg0 + nt * 8 + 2 * (lane & 3);
                const float* p = &g_xpre[((size_t)t * 512 + row) * NSEQ + sq];
                float2 v = __ldg(reinterpret_cast<const float2*>(p));
                float2 u = __ldg(reinterpret_cast<const float2*>(p + (size_t)8 * NSEQ));
                C[mt][nt][0] = v.x; C[mt][nt][1] = v.y; C[mt][nt][2] = u.x; C[mt][nt][3] = u.y;
            }
        // ---- MMA over h (K=128), 3-term bf16 split ----
        const uint32_t* pb = (const uint32_t*)sB16;
        #pragma unroll
        for (int kt = 0; kt < 8; kt++) {
            uint32_t Ah[2][4];
            #pragma unroll
            for (int mt = 0; mt < 2; mt++) {
                const uint32_t* p = &sW[(kt * 32 + (2 * w + mt)) * 128 + lane * 4];
                #pragma unroll
                for (int q = 0; q < 4; q++) Ah[mt][q] = p[q];
            }
            #pragma unroll
            for (int nt = 0; nt < 3; nt++) {
                uint32_t bh0 = pb[((0 * 8 + kt) * 3 + nt) * 64 + lane * 2];
                uint32_t bh1 = pb[((0 * 8 + kt) * 3 + nt) * 64 + lane * 2 + 1];
                uint32_t bl0 = pb[((1 * 8 + kt) * 3 + nt) * 64 + lane * 2];
                uint32_t bl1 = pb[((1 * 8 + kt) * 3 + nt) * 64 + lane * 2 + 1];
                #pragma unroll
                for (int mt = 0; mt < 2; mt++) {
                    mma_bf16(C[mt][nt], Ah[mt], bh0, bh1);
                    mma_bf16(C[mt][nt], wlo[mt][kt], bh0, bh1);
                    mma_bf16(C[mt][nt], Ah[mt], bl0, bl1);
                }
            }
        }
        // ---- scatter pre-acts to sact[row][seq] ----
        #pragma unroll
        for (int mt = 0; mt < 2; mt++)
            #pragma unroll
            for (int nt = 0; nt < 3; nt++) {
                int row = (2 * w + mt) * 16 + (lane >> 2);
                int sq  = nt * 8 + 2 * (lane & 3);
                *reinterpret_cast<float2*>(&sact[row * 24 + sq]) = make_float2(C[mt][nt][0], C[mt][nt][1]);
                *reinterpret_cast<float2*>(&sact[(row + 8) * 24 + sq]) = make_float2(C[mt][nt][2], C[mt][nt][3]);
            }
        __syncthreads();

        // ---- cell update: thread owns cell j, 6 seqs; writes h + B-frag images ----
        #pragma unroll
        for (int e = 0; e < 6; e++) {
            int s = sgrp * 6 + e;
            float gi = sact[j * 24 + s]         + bi_;
            float gf = sact[(128 + j) * 24 + s] + bf_;
            float gg = sact[(256 + j) * 24 + s] + bg_;
            float go = sact[(384 + j) * 24 + s] + bo_;
            float cc = sigf(gf) * cs[e] + sigf(gi) * tanhf_(gg);
            cs[e] = cc;
            float h = sigf(go) * tanhf_(cc);
            sh[s * 128 + j] = h;
            __nv_bfloat16 hb = __float2bfloat16_rn(h);
            __nv_bfloat16 lb = __float2bfloat16_rn(h - __bfloat162float(hb));
            int kt = j >> 4, kk = j & 15, nt = s >> 3;
            int lb_ = (s & 7) * 4 + ((kk & 7) >> 1), reg = kk >> 3, half = kk & 1;
            sB16[(((0 * 8 + kt) * 3 + nt) * 32 + lb_) * 4 + reg * 2 + half] = *reinterpret_cast<uint16_t*>(&hb);
            sB16[(((1 * 8 + kt) * 3 + nt) * 32 + lb_) * 4 + reg * 2 + half] = *reinterpret_cast<uint16_t*>(&lb);
        }
        __syncthreads();

        // ---- fused note-LSTM input projection ----
        if (tid < SPB1 * 8) {
            int s = tid >> 3, row = tid & 7;
            const float2* hv = reinterpret_cast<const float2*>(&sh[s * 128]);
            const float2* wv = reinterpret_cast<const float2*>(&sWn[row * 128]);
            float a = 0.f;
            #pragma unroll
            for (int jj = 0; jj < 64; jj++) {
                float2 h2 = hv[jj], w2 = wv[jj];
                a = fmaf(h2.x, w2.x, fmaf(h2.y, w2.y, a));
            }
            g_xpj[((size_t)(sg0 + s) * T_ + t) * 8 + row] = a;
        }
        __syncthreads();
    }
}

// ---------------- stage 2: note LSTM (hidden=2), one thread per (b,t) ----------------
__global__ __launch_bounds__(128) void stage2_kernel(
    const float* __restrict__ Whhn,
    const float* __restrict__ bihn, const float* __restrict__ bhhn,
    float* __restrict__ out)
{
    int g = blockIdx.x * 128 + threadIdx.x;
    int b = g >> 7, t = g & 127;
    float W[16];
    #pragma unroll
    for (int i = 0; i < 16; i++) W[i] = Whhn[i];
    float bs[8];
    #pragma unroll
    for (int i = 0; i < 8; i++) bs[i] = bihn[i] + bhhn[i];
    float h0 = 0.f, h1 = 0.f, c0 = 0.f, c1 = 0.f;
    const float4* xp = reinterpret_cast<const float4*>(g_xpj);
    float* op = out + ((size_t)b * T_ + t) * (NOTES_ * 2);
    for (int note = 0; note < NOTES_; note++) {
        size_t base = ((size_t)(b * NOTES_ + note) * T_ + t) * 2;
        float4 xa = xp[base], xb = xp[base + 1];
        float gi0 = xa.x + bs[0] + W[0]  * h0 + W[1]  * h1;
        float gi1 = xa.y + bs[1] + W[2]  * h0 + W[3]  * h1;
        float gf0 = xa.z + bs[2] + W[4]  * h0 + W[5]  * h1;
        float gf1 = xa.w + bs[3] + W[6]  * h0 + W[7]  * h1;
        float gg0 = xb.x + bs[4] + W[8]  * h0 + W[9]  * h1;
        float gg1 = xb.y + bs[5] + W[10] * h0 + W[11] * h1;
        float go0 = xb.z + bs[6] + W[12] * h0 + W[13] * h1;
        float go1 = xb.w + bs[7] + W[14] * h0 + W[15] * h1;
        c0 = sigf(gf0) * c0 + sigf(gi0) * tanhf_(gg0);
        c1 = sigf(gf1) * c1 + sigf(gi1) * tanhf_(gg1);
        h0 = sigf(go0) * tanhf_(c0);
        h1 = sigf(go1) * tanhf_(c1);
        op[note * 2] = h0; op[note * 2 + 1] = h1;
    }
}

// ---------------- launch ----------------
extern "C" void kernel_launch(void* const* d_in, const int* in_sizes, int n_in,
                              void* d_out, int out_size)
{
    const float* x     = (const float*)d_in[0];
    const float* Wih_t = (const float*)d_in[1];
    const float* Whh_t = (const float*)d_in[2];
    const float* bih_t = (const float*)d_in[3];
    const float* bhh_t = (const float*)d_in[4];
    const float* Wih_n = (const float*)d_in[5];
    const float* Whh_n = (const float*)d_in[6];
    const float* bih_n = (const float*)d_in[7];
    const float* bhh_n = (const float*)d_in[8];
    float* out = (float*)d_out;

    const int smx = (40960 + 5120) * 4;                                   // 184320
    const int sm1 = 32768 * 4 + 3072 * 4 + (512 * 24 + 24 * 128 + 1024) * 4; // 208896
    cudaFuncSetAttribute(xproj_kernel,  cudaFuncAttributeMaxDynamicSharedMemorySize, smx);
    cudaFuncSetAttribute(stage1_kernel, cudaFuncAttributeMaxDynamicSharedMemorySize, sm1);

    pack_kernel<<<(106496 + 255) / 256, 256>>>(Wih_t, Whh_t);   // launch 1
    xproj_kernel<<<39 * 32, 512, smx>>>(x);                     // launch 2
    dummy_kernel<<<1, 32>>>();                                  // 3
    dummy_kernel<<<1, 32>>>();                                  // 4
    dummy_kernel<<<1, 32>>>();                                  // 5
    stage1_kernel<<<104, 512, sm1>>>(bih_t, bhh_t, Wih_n);      // 6 (ncu -s 5 lands here)
    stage2_kernel<<<(B_ * T_) / 128, 128>>>(Whh_n, bih_n, bhh_n, out);
}

// round 12
// speedup vs baseline: 1.7770x; 1.1318x over previous
#include <cuda_runtime.h>
#include <cuda_bf16.h>
#include <cstdint>

#define B_     32
#define NOTES_ 78
#define T_     128
#define NSEQ   2496
#define SPB    24
#define NBLK   104

// ---------------- device scratch ----------------
__device__ uint32_t g_whhA[2 * 8 * 32 * 128];      // Whh A-frag image [hf][kt][mt][lane][q]
__device__ uint32_t g_wxA [2 * 5 * 32 * 128];      // Wih A-frag image
__device__ float    g_xpre[(size_t)T_ * 512 * NSEQ];
__device__ float    g_xpj[(size_t)NSEQ * T_ * 8];

// ---------------- helpers ----------------
__device__ __forceinline__ float sigf(float x)   { return __fdividef(1.f, 1.f + __expf(-x)); }
__device__ __forceinline__ float tanhf_(float x) { return 2.f * sigf(2.f * x) - 1.f; }
__device__ __forceinline__ uint32_t bfhi2(float a, float b) {
    __nv_bfloat162 t = __floats2bfloat162_rn(a, b);
    return *reinterpret_cast<uint32_t*>(&t);
}
__device__ __forceinline__ uint32_t bflo2(float a, float b) {
    __nv_bfloat16 ha = __float2bfloat16_rn(a), hb = __float2bfloat16_rn(b);
    return bfhi2(a - __bfloat162float(ha), b - __bfloat162float(hb));
}
__device__ __forceinline__ void mma_bf16(float* c, const uint32_t* a, uint32_t b0, uint32_t b1) {
    asm volatile("mma.sync.aligned.m16n8k16.row.col.f32.bf16.bf16.f32 "
        "{%0,%1,%2,%3},{%4,%5,%6,%7},{%8,%9},{%0,%1,%2,%3};"
        : "+f"(c[0]), "+f"(c[1]), "+f"(c[2]), "+f"(c[3])
        : "r"(a[0]), "r"(a[1]), "r"(a[2]), "r"(a[3]), "r"(b0), "r"(b1));
}

// ---------------- pack (R10-validated mapping) ----------------
__global__ void pack_kernel(const float* __restrict__ Wih, const float* __restrict__ Whh) {
    int i = blockIdx.x * 256 + threadIdx.x;
    if (i < 65536) {                         // Whh: [hf][kt8][mt32][lane][q]
        int q = i & 3, lane = (i >> 2) & 31, hf = i >> 15;
        int row = ((i >> 7) & 31) * 16 + (lane >> 2) + (q & 1) * 8;
        int k   = ((i >> 12) & 7) * 16 + 2 * (lane & 3) + (q >> 1) * 8;
        float v0 = Whh[row * 128 + k], v1 = Whh[row * 128 + k + 1];
        g_whhA[i] = hf ? bflo2(v0, v1) : bfhi2(v0, v1);
    } else if (i < 106496) {                 // Wih: [hf][kt5][mt][lane][q]
        int j = i - 65536;
        int q = j & 3, lane = (j >> 2) & 31;
        int r = j >> 12, kt = r % 5, hf = r / 5;
        int row = ((j >> 7) & 31) * 16 + (lane >> 2) + (q & 1) * 8;
        int k = kt * 16 + 2 * (lane & 3) + (q >> 1) * 8;
        float v0 = Wih[row * 80 + k], v1 = Wih[row * 80 + k + 1];
        g_wxA[j] = hf ? bflo2(v0, v1) : bfhi2(v0, v1);
    }
}

// ---------------- xproj (R10 verbatim) ----------------
__global__ __launch_bounds__(512, 1) void xproj_kernel(const float* __restrict__ x) {
    extern __shared__ uint32_t smx[];
    uint32_t* sWx = smx;
    uint32_t* sB  = smx + 40960;
    const int tid = threadIdx.x, w = tid >> 5, lane = tid & 31;
    const int sg0 = (blockIdx.x >> 5) * 64;
    const int tb  = (blockIdx.x & 31) * 4;
    for (int i = tid; i < 40960; i += 512) sWx[i] = g_wxA[i];
    for (int tt = 0; tt < 4; tt++) {
        const int t = tb + tt;
        __syncthreads();
        for (int r = 0; r < 3; r++) {
            int idx = tid + r * 512;
            if (idx < 1280) {
                int s = idx / 20, qq = idx - s * 20, k0 = qq * 4;
                float4 v = *reinterpret_cast<const float4*>(&x[((size_t)(sg0 + s) * T_ + t) * 80 + k0]);
                int kt = k0 >> 4, kk = k0 & 15, nt = s >> 3;
                int lb = (s & 7) * 4 + ((kk & 7) >> 1), reg = kk >> 3;
                uint32_t* ph = &sB[((0 * 5 + kt) * 8 + nt) * 64 + lb * 2 + reg];
                uint32_t* pl = &sB[((1 * 5 + kt) * 8 + nt) * 64 + lb * 2 + reg];
                ph[0] = bfhi2(v.x, v.y); ph[2] = bfhi2(v.z, v.w);
                pl[0] = bflo2(v.x, v.y); pl[2] = bflo2(v.z, v.w);
            }
        }
        __syncthreads();
        float C[2][8][4];
        #pragma unroll
        for (int a = 0; a < 2; a++)
            #pragma unroll
            for (int n = 0; n < 8; n++)
                #pragma unroll
                for (int q = 0; q < 4; q++) C[a][n][q] = 0.f;
        #pragma unroll
        for (int kt = 0; kt < 5; kt++) {
            uint32_t Ah[2][4], Al[2][4];
            #pragma unroll
            for (int mt = 0; mt < 2; mt++) {
                const uint32_t* p  = &sWx[((0 * 5 + kt) * 32 + (2 * w + mt)) * 128 + lane * 4];
                const uint32_t* p2 = &sWx[((1 * 5 + kt) * 32 + (2 * w + mt)) * 128 + lane * 4];
                #pragma unroll
                for (int q = 0; q < 4; q++) { Ah[mt][q] = p[q]; Al[mt][q] = p2[q]; }
            }
            #pragma unroll
            for (int nt = 0; nt < 8; nt++) {
                uint32_t bh0 = sB[((0 * 5 + kt) * 8 + nt) * 64 + lane * 2];
                uint32_t bh1 = sB[((0 * 5 + kt) * 8 + nt) * 64 + lane * 2 + 1];
                uint32_t bl0 = sB[((1 * 5 + kt) * 8 + nt) * 64 + lane * 2];
                uint32_t bl1 = sB[((1 * 5 + kt) * 8 + nt) * 64 + lane * 2 + 1];
                #pragma unroll
                for (int mt = 0; mt < 2; mt++) {
                    mma_bf16(C[mt][nt], Ah[mt], bh0, bh1);
                    mma_bf16(C[mt][nt], Al[mt], bh0, bh1);
                    mma_bf16(C[mt][nt], Ah[mt], bl0, bl1);
                }
            }
        }
        #pragma unroll
        for (int mt = 0; mt < 2; mt++)
            #pragma unroll
            for (int nt = 0; nt < 8; nt++) {
                int row = (2 * w + mt) * 16 + (lane >> 2);
                int sq  = sg0 + nt * 8 + 2 * (lane & 3);
                float* d = &g_xpre[((size_t)t * 512 + row) * NSEQ + sq];
                *reinterpret_cast<float2*>(d) = make_float2(C[mt][nt][0], C[mt][nt][1]);
                *reinterpret_cast<float2*>(d + (size_t)8 * NSEQ) = make_float2(C[mt][nt][2], C[mt][nt][3]);
            }
    }
}

// ---------------- stage 1: warp-specialized HMMA LSTM ----------------
// smem: sAhi u32[32768] (128KB) | xq f[512*24] (48KB) | sB16 u16[2][6144] (24KB)
//       | sh f[24*128] (12KB) | sWnT float2[512] (4KB)   = 221184 B
__global__ __launch_bounds__(512, 1) void stage1_kernel(
    const float* __restrict__ bih, const float* __restrict__ bhh,
    const float* __restrict__ Wihn)
{
    extern __shared__ __align__(16) char sm[];
    uint32_t* sAhi = (uint32_t*)sm;
    float*    xq   = (float*)(sm + 131072);
    uint16_t* sB16 = (uint16_t*)(sm + 180224);
    float*    sh   = (float*)(sm + 204800);
    float2*   sWnT = (float2*)(sm + 217088);

    const int tid = threadIdx.x, w = tid >> 5, l = tid & 31;
    const int seq0 = blockIdx.x * SPB;
    const bool ismma = (w < 8);
    const int r1 = (w & 7) * 16 + (l >> 2), r2 = r1 + 8;

    for (int i = tid; i < 32768; i += 512) sAhi[i] = g_whhA[i];
    for (int i = tid; i < 6144; i += 512) ((uint32_t*)sB16)[i] = 0;   // zero both B buffers
    sWnT[tid] = make_float2(Wihn[(tid & 7) * 128 + 2 * (tid >> 3)],
                            Wihn[(tid & 7) * 128 + 2 * (tid >> 3) + 1]);
    {   // stage xq(0): thread = row
        const float4* p = (const float4*)&g_xpre[(size_t)tid * NSEQ + seq0];
        float4* q = (float4*)&xq[tid * 24];
        #pragma unroll
        for (int i = 0; i < 6; i++) q[i] = p[i];
    }

    float b4[4][2];
    if (ismma) {
        #pragma unroll
        for (int g = 0; g < 4; g++) {
            b4[g][0] = bih[g * 128 + r1] + bhh[g * 128 + r1];
            b4[g][1] = bih[g * 128 + r2] + bhh[g * 128 + r2];
        }
    }
    float cs[3][4];
    #pragma unroll
    for (int nt = 0; nt < 3; nt++)
        #pragma unroll
        for (int q = 0; q < 4; q++) cs[nt][q] = 0.f;

    __syncthreads();

    for (int t = 0; t < T_; t++) {
        float C[4][3][4];
        if (ismma) {          // C init from xq(t)
            #pragma unroll
            for (int g = 0; g < 4; g++)
                #pragma unroll
                for (int nt = 0; nt < 3; nt++) {
                    int sqb = nt * 8 + 2 * (l & 3);
                    float2 v  = *(const float2*)&xq[(g * 128 + r1) * 24 + sqb];
                    float2 u2 = *(const float2*)&xq[(g * 128 + r2) * 24 + sqb];
                    C[g][nt][0] = v.x; C[g][nt][1] = v.y; C[g][nt][2] = u2.x; C[g][nt][3] = u2.y;
                }
        }
        __syncthreads();      // S1: xq(t) consumed

        if (ismma) {
            const uint32_t* pb = (const uint32_t*)(sB16 + (t & 1) * 6144);
            uint4 rlo[6];     // Whh-lo LDG ring, depth 6
            #pragma unroll
            for (int u = 0; u < 6; u++)
                rlo[u] = *(const uint4*)&g_whhA[32768 + ((u >> 2) * 32 + (u & 3) * 8 + w) * 128 + l * 4];
            #pragma unroll
            for (int kt = 0; kt < 8; kt++) {
                uint32_t bh[3][2], bl[3][2];
                #pragma unroll
                for (int nt = 0; nt < 3; nt++) {
                    uint2 v = *(const uint2*)&pb[((0 * 8 + kt) * 3 + nt) * 64 + l * 2];
                    bh[nt][0] = v.x; bh[nt][1] = v.y;
                    uint2 v2 = *(const uint2*)&pb[((1 * 8 + kt) * 3 + nt) * 64 + l * 2];
                    bl[nt][0] = v2.x; bl[nt][1] = v2.y;
                }
                #pragma unroll
                for (int g = 0; g < 4; g++) {
                    const int u = kt * 4 + g;
                    uint4 ah4 = *(const uint4*)&sAhi[(kt * 32 + g * 8 + w) * 128 + l * 4];
                    uint32_t Ahi[4] = {ah4.x, ah4.y, ah4.z, ah4.w};
                    uint4 alv = rlo[u % 6];
                    if (u < 26) {
                        const int u2 = u + 6;
                        rlo[u % 6] = *(const uint4*)&g_whhA[32768 + ((u2 >> 2) * 32 + (u2 & 3) * 8 + w) * 128 + l * 4];
                    }
                    uint32_t Alo[4] = {alv.x, alv.y, alv.z, alv.w};
                    #pragma unroll
                    for (int nt = 0; nt < 3; nt++) {
                        mma_bf16(C[g][nt], Ahi, bh[nt][0], bh[nt][1]);
                        mma_bf16(C[g][nt], Alo, bh[nt][0], bh[nt][1]);
                        mma_bf16(C[g][nt], Ahi, bl[nt][0], bl[nt][1]);
                    }
                }
            }
        } else {
            const int at = tid - 256;
            if (t < T_ - 1) {     // stage xq(t+1): 2 rows per aux thread
                #pragma unroll
                for (int rr = 0; rr < 2; rr++) {
                    int row = at * 2 + rr;
                    const float4* p = (const float4*)&g_xpre[((size_t)(t + 1) * 512 + row) * NSEQ + seq0];
                    float4* q = (float4*)&xq[row * 24];
                    #pragma unroll
                    for (int i = 0; i < 6; i++) q[i] = p[i];
                }
            }
            if (t > 0 && at < 192) {   // note-proj for t-1
                int s = at >> 3, r8 = at & 7;
                const float2* hv = (const float2*)&sh[s * 128];
                float acc = 0.f;
                #pragma unroll
                for (int jj = 0; jj < 64; jj++) {
                    float2 h2 = hv[jj], w2 = sWnT[jj * 8 + r8];
                    acc = fmaf(h2.x, w2.x, fmaf(h2.y, w2.y, acc));
                }
                g_xpj[((size_t)(seq0 + s) * T_ + (t - 1)) * 8 + r8] = acc;
            }
        }
        __syncthreads();      // S2: aux done with sh(t-1) + xq staged

        if (ismma) {          // in-register LSTM update + writeback
            uint16_t* dst = sB16 + ((t & 1) ^ 1) * 6144;
            #pragma unroll
            for (int nt = 0; nt < 3; nt++)
                #pragma unroll
                for (int q = 0; q < 4; q++) {
                    const int rsel = q >> 1;
                    const int row = rsel ? r2 : r1;
                    const int s = nt * 8 + 2 * (l & 3) + (q & 1);
                    float gi = C[0][nt][q] + b4[0][rsel];
                    float gf = C[1][nt][q] + b4[1][rsel];
                    float gg = C[2][nt][q] + b4[2][rsel];
                    float go = C[3][nt][q] + b4[3][rsel];
                    float cc = sigf(gf) * cs[nt][q] + sigf(gi) * tanhf_(gg);
                    cs[nt][q] = cc;
                    float h = sigf(go) * tanhf_(cc);
                    sh[s * 128 + row] = h;
                    __nv_bfloat16 hb = __float2bfloat16_rn(h);
                    float lof = h - __bfloat162float(hb);
                    __nv_bfloat16 lb = __float2bfloat16_rn(lof);
                    const int kt = row >> 4, kk = row & 15;
                    const int lane2 = (s & 7) * 4 + ((kk & 7) >> 1), reg = kk >> 3, half = kk & 1;
                    dst[(((0 * 8 + kt) * 3 + nt) * 32 + lane2) * 4 + reg * 2 + half] =
                        *reinterpret_cast<uint16_t*>(&hb);
                    dst[(((1 * 8 + kt) * 3 + nt) * 32 + lane2) * 4 + reg * 2 + half] =
                        *reinterpret_cast<uint16_t*>(&lb);
                }
        }
        __syncthreads();      // S3: B(t), sh(t) visible
    }

    if (tid < 192) {          // final note-proj, t = 127
        int s = tid >> 3, r8 = tid & 7;
        const float2* hv = (const float2*)&sh[s * 128];
        float acc = 0.f;
        #pragma unroll
        for (int jj = 0; jj < 64; jj++) {
            float2 h2 = hv[jj], w2 = sWnT[jj * 8 + r8];
            acc = fmaf(h2.x, w2.x, fmaf(h2.y, w2.y, acc));
        }
        g_xpj[((size_t)(seq0 + s) * T_ + (T_ - 1)) * 8 + r8] = acc;
    }
}

// ---------------- stage 2 (R10 verbatim) ----------------
__global__ __launch_bounds__(128) void stage2_kernel(
    const float* __restrict__ Whhn,
    const float* __restrict__ bihn, const float* __restrict__ bhhn,
    float* __restrict__ out)
{
    int g = blockIdx.x * 128 + threadIdx.x;
    int b = g >> 7, t = g & 127;
    float W[16];
    #pragma unroll
    for (int i = 0; i < 16; i++) W[i] = Whhn[i];
    float bs[8];
    #pragma unroll
    for (int i = 0; i < 8; i++) bs[i] = bihn[i] + bhhn[i];
    float h0 = 0.f, h1 = 0.f, c0 = 0.f, c1 = 0.f;
    const float4* xp = reinterpret_cast<const float4*>(g_xpj);
    float* op = out + ((size_t)b * T_ + t) * (NOTES_ * 2);
    for (int note = 0; note < NOTES_; note++) {
        size_t base = ((size_t)(b * NOTES_ + note) * T_ + t) * 2;
        float4 xa = xp[base], xb = xp[base + 1];
        float gi0 = xa.x + bs[0] + W[0]  * h0 + W[1]  * h1;
        float gi1 = xa.y + bs[1] + W[2]  * h0 + W[3]  * h1;
        float gf0 = xa.z + bs[2] + W[4]  * h0 + W[5]  * h1;
        float gf1 = xa.w + bs[3] + W[6]  * h0 + W[7]  * h1;
        float gg0 = xb.x + bs[4] + W[8]  * h0 + W[9]  * h1;
        float gg1 = xb.y + bs[5] + W[10] * h0 + W[11] * h1;
        float go0 = xb.z + bs[6] + W[12] * h0 + W[13] * h1;
        float go1 = xb.w + bs[7] + W[14] * h0 + W[15] * h1;
        c0 = sigf(gf0) * c0 + sigf(gi0) * tanhf_(gg0);
        c1 = sigf(gf1) * c1 + sigf(gi1) * tanhf_(gg1);
        h0 = sigf(go0) * tanhf_(c0);
        h1 = sigf(go1) * tanhf_(c1);
        op[note * 2] = h0; op[note * 2 + 1] = h1;
    }
}

// ---------------- launch ----------------
extern "C" void kernel_launch(void* const* d_in, const int* in_sizes, int n_in,
                              void* d_out, int out_size)
{
    const float* x     = (const float*)d_in[0];
    const float* Wih_t = (const float*)d_in[1];
    const float* Whh_t = (const float*)d_in[2];
    const float* bih_t = (const float*)d_in[3];
    const float* bhh_t = (const float*)d_in[4];
    const float* Wih_n = (const float*)d_in[5];
    const float* Whh_n = (const float*)d_in[6];
    const float* bih_n = (const float*)d_in[7];
    const float* bhh_n = (const float*)d_in[8];
    float* out = (float*)d_out;

    const int smx = (40960 + 5120) * 4;   // 184320
    const int sm1 = 221184;
    cudaFuncSetAttribute(xproj_kernel,  cudaFuncAttributeMaxDynamicSharedMemorySize, smx);
    cudaFuncSetAttribute(stage1_kernel, cudaFuncAttributeMaxDynamicSharedMemorySize, sm1);

    pack_kernel<<<(106496 + 255) / 256, 256>>>(Wih_t, Whh_t);
    xproj_kernel<<<39 * 32, 512, smx>>>(x);
    stage1_kernel<<<NBLK, 512, sm1>>>(bih_t, bhh_t, Wih_n);
    stage2_kernel<<<(B_ * T_) / 128, 128>>>(Whh_n, bih_n, bhh_n, out);
}